// round 2
// baseline (speedup 1.0000x reference)
#include <cuda_runtime.h>
#include <math_constants.h>

#define N 512
#define BATCH 256
#define CHUNKS 8              // blocks per batch row in the main reduction
#define TPB 256               // threads per block, kernel B

// Scratch (no device allocs allowed in kernel_launch)
__device__ float g_u[N];
__device__ float g_v[N];
__device__ float g_partial2[BATCH][CHUNKS];

// ---------------------------------------------------------------------------
// Kernel A: u[k] = sum_i w_h[i]*cu(i)*cos((2k+1) i pi / (2N))  (same for v).
// basis[i,k] = cu[i] * cos((2k+1) * i * pi / (2N)); u = B^T w_h, v = B^T w_v.
// 1 block, 512 threads. Arg of cospif: (2k+1)*i/1024, numerator < 2^24 (exact).
// ---------------------------------------------------------------------------
__global__ void proj_kernel(const float* __restrict__ wh,
                            const float* __restrict__ wv) {
    int k = threadIdx.x;           // frequency-sample index 0..511
    float su = 0.f, sv = 0.f;
    const float c0 = sqrtf(1.0f / N);
    const float c1 = sqrtf(2.0f / N);
    float two_k_p1 = (float)(2 * k + 1);
    #pragma unroll 4
    for (int i = 0; i < N; ++i) {
        float cu = (i == 0) ? c0 : c1;
        // t = (2k+1)*i / (2N); cos(pi * t)
        float t = two_k_p1 * (float)i * (1.0f / (2.0f * N));
        float c = cospif(t) * cu;
        su = fmaf(wh[i], c, su);
        sv = fmaf(wv[i], c, sv);
    }
    g_u[k] = su;
    g_v[k] = sv;
}

// ---------------------------------------------------------------------------
// Kernel B: streaming weighted reduction.
// grid = (CHUNKS, BATCH). Each block handles 65536/CHUNKS float4 of one row.
// g_partial2[b][c] = sum over chunk of x[b,e] * u[e>>9] * v[e&511]
// Deterministic: fixed reduction tree, no atomics.
// ---------------------------------------------------------------------------
__global__ void __launch_bounds__(TPB)
reduce_kernel(const float* __restrict__ x) {
    const int b = blockIdx.y;
    const int c = blockIdx.x;
    const int t = threadIdx.x;

    const int f4_per_row   = (N * N) / 4;         // 65536
    const int f4_per_chunk = f4_per_row / CHUNKS; // 8192
    const int iters        = f4_per_chunk / TPB;  // 32

    const float4* __restrict__ xr =
        reinterpret_cast<const float4*>(x) + (size_t)b * f4_per_row + c * f4_per_chunk;

    float acc = 0.f;
    #pragma unroll 8
    for (int i = 0; i < iters; ++i) {
        int f = i * TPB + t;                 // float4 index within chunk
        float4 xv = xr[f];
        int e = (c * f4_per_chunk + f) * 4;  // element index within row
        int k = e >> 9;                      // row of the 512x512 image
        int l = e & 511;                     // col (l..l+3 same row: 512%4==0)
        float uk = g_u[k];
        float dot = fmaf(xv.x, g_v[l],
                    fmaf(xv.y, g_v[l + 1],
                    fmaf(xv.z, g_v[l + 2],
                         xv.w * g_v[l + 3])));
        acc = fmaf(uk, dot, acc);
    }

    // block reduction (deterministic tree)
    __shared__ float red[TPB / 32];
    #pragma unroll
    for (int o = 16; o > 0; o >>= 1)
        acc += __shfl_down_sync(0xffffffffu, acc, o);
    if ((t & 31) == 0) red[t >> 5] = acc;
    __syncthreads();
    if (t < TPB / 32) {
        float s = red[t];
        #pragma unroll
        for (int o = (TPB / 64); o > 0; o >>= 1)
            s += __shfl_down_sync(0xffffffffu, s, o);
        if (t == 0) g_partial2[b][c] = s;
    }
}

// ---------------------------------------------------------------------------
// Kernel C: out[b] = sigmoid(sum_c partial[b][c] + bias)
// ---------------------------------------------------------------------------
__global__ void finish_kernel(const float* __restrict__ bias,
                              float* __restrict__ out) {
    int b = threadIdx.x;
    if (b < BATCH) {
        float r = bias[0];
        #pragma unroll
        for (int c = 0; c < CHUNKS; ++c) r += g_partial2[b][c];
        out[b] = 1.0f / (1.0f + __expf(-r));
    }
}

extern "C" void kernel_launch(void* const* d_in, const int* in_sizes, int n_in,
                              void* d_out, int out_size) {
    const float* x    = (const float*)d_in[0];
    const float* wh   = (const float*)d_in[1];
    const float* wv   = (const float*)d_in[2];
    const float* bias = (const float*)d_in[3];
    float* out = (float*)d_out;

    proj_kernel<<<1, N>>>(wh, wv);
    dim3 grid(CHUNKS, BATCH);
    reduce_kernel<<<grid, TPB>>>(x);
    finish_kernel<<<1, BATCH>>>(bias, out);
}

// round 3
// speedup vs baseline: 1.7595x; 1.7595x over previous
#include <cuda_runtime.h>
#include <math_constants.h>

#define N 512
#define BATCH 256
#define CHUNKS 8              // blocks per batch row in the main reduction
#define TPB 256               // threads per block, kernel B
#define PROJ_TPB 128          // threads per block, kernel A

// Scratch (no device allocs allowed in kernel_launch)
__device__ float g_u[N];
__device__ float g_v[N];
__device__ float g_partial2[BATCH][CHUNKS];

// ---------------------------------------------------------------------------
// Kernel A (parallel): u[k] = sum_i w_h[i]*cu(i)*cos((2k+1) i pi / (2N)),
// same for v. One block per k (512 blocks), 128 threads each; each thread
// covers i = t, t+128, t+256, t+384; deterministic tree reduction.
// cospif arg: (2k+1)*i/1024, numerator < 2^24 so it's exact in fp32.
// ---------------------------------------------------------------------------
__global__ void __launch_bounds__(PROJ_TPB)
proj_kernel(const float* __restrict__ wh, const float* __restrict__ wv) {
    const int k = blockIdx.x;          // frequency-sample index 0..511
    const int t = threadIdx.x;

    const float c0 = sqrtf(1.0f / N);
    const float c1 = sqrtf(2.0f / N);
    const float two_k_p1 = (float)(2 * k + 1);

    float su = 0.f, sv = 0.f;
    #pragma unroll
    for (int r = 0; r < N / PROJ_TPB; ++r) {
        int i = r * PROJ_TPB + t;
        float cu = (i == 0) ? c0 : c1;
        float tt = two_k_p1 * (float)i * (1.0f / (2.0f * N));
        float c = cospif(tt) * cu;
        su = fmaf(wh[i], c, su);
        sv = fmaf(wv[i], c, sv);
    }

    // deterministic block reduction (128 threads = 4 warps)
    __shared__ float ru[PROJ_TPB / 32], rv[PROJ_TPB / 32];
    #pragma unroll
    for (int o = 16; o > 0; o >>= 1) {
        su += __shfl_down_sync(0xffffffffu, su, o);
        sv += __shfl_down_sync(0xffffffffu, sv, o);
    }
    if ((t & 31) == 0) { ru[t >> 5] = su; rv[t >> 5] = sv; }
    __syncthreads();
    if (t == 0) {
        float fu = ru[0] + ru[1] + ru[2] + ru[3];
        float fv = rv[0] + rv[1] + rv[2] + rv[3];
        g_u[k] = fu;
        g_v[k] = fv;
    }
}

// ---------------------------------------------------------------------------
// Kernel B: streaming weighted reduction (at HBM roofline — unchanged).
// grid = (CHUNKS, BATCH). Each block handles 65536/CHUNKS float4 of one row.
// g_partial2[b][c] = sum over chunk of x[b,e] * u[e>>9] * v[e&511]
// ---------------------------------------------------------------------------
__global__ void __launch_bounds__(TPB)
reduce_kernel(const float* __restrict__ x) {
    const int b = blockIdx.y;
    const int c = blockIdx.x;
    const int t = threadIdx.x;

    const int f4_per_row   = (N * N) / 4;         // 65536
    const int f4_per_chunk = f4_per_row / CHUNKS; // 8192
    const int iters        = f4_per_chunk / TPB;  // 32

    const float4* __restrict__ xr =
        reinterpret_cast<const float4*>(x) + (size_t)b * f4_per_row + c * f4_per_chunk;

    float acc = 0.f;
    #pragma unroll 8
    for (int i = 0; i < iters; ++i) {
        int f = i * TPB + t;                 // float4 index within chunk
        float4 xv = xr[f];
        int e = (c * f4_per_chunk + f) * 4;  // element index within row
        int k = e >> 9;                      // row of the 512x512 image
        int l = e & 511;                     // col (l..l+3 same row: 512%4==0)
        float uk = g_u[k];
        float dot = fmaf(xv.x, g_v[l],
                    fmaf(xv.y, g_v[l + 1],
                    fmaf(xv.z, g_v[l + 2],
                         xv.w * g_v[l + 3])));
        acc = fmaf(uk, dot, acc);
    }

    // block reduction (deterministic tree)
    __shared__ float red[TPB / 32];
    #pragma unroll
    for (int o = 16; o > 0; o >>= 1)
        acc += __shfl_down_sync(0xffffffffu, acc, o);
    if ((t & 31) == 0) red[t >> 5] = acc;
    __syncthreads();
    if (t < TPB / 32) {
        float s = red[t];
        #pragma unroll
        for (int o = (TPB / 64); o > 0; o >>= 1)
            s += __shfl_down_sync(0xffffffffu, s, o);
        if (t == 0) g_partial2[b][c] = s;
    }
}

// ---------------------------------------------------------------------------
// Kernel C: out[b] = sigmoid(sum_c partial[b][c] + bias)
// ---------------------------------------------------------------------------
__global__ void finish_kernel(const float* __restrict__ bias,
                              float* __restrict__ out) {
    int b = threadIdx.x;
    if (b < BATCH) {
        float r = bias[0];
        #pragma unroll
        for (int c = 0; c < CHUNKS; ++c) r += g_partial2[b][c];
        out[b] = 1.0f / (1.0f + __expf(-r));
    }
}

extern "C" void kernel_launch(void* const* d_in, const int* in_sizes, int n_in,
                              void* d_out, int out_size) {
    const float* x    = (const float*)d_in[0];
    const float* wh   = (const float*)d_in[1];
    const float* wv   = (const float*)d_in[2];
    const float* bias = (const float*)d_in[3];
    float* out = (float*)d_out;

    proj_kernel<<<N, PROJ_TPB>>>(wh, wv);
    dim3 grid(CHUNKS, BATCH);
    reduce_kernel<<<grid, TPB>>>(x);
    finish_kernel<<<1, BATCH>>>(bias, out);
}